// round 9
// baseline (speedup 1.0000x reference)
#include <cuda_runtime.h>
#include <cstdint>

// out[n] = embedding[hash(trunc(x[n]*128))]  (reference's xf==0 collapses the
// trilerp to corner 0, weight 1; bit-exact).
// hash = (u0 ^ u1*2654435761 ^ u2*805459861) & (2^19 - 1)
//
// R9: ALL gathers via the TMA engine. Every LDG-family kernel plateaus at
// ~39K cyc/SM = 14.2K random rows / (≈90 outstanding L1 sectors / ≈250cyc L2
// latency) — a structural L1tex miss-queue cap. The TMA engine has its own
// deep queue; R7 measured ≈1.7 cyc engine occupancy per 32B bulk op. Each
// thread hashes 4 points and fires 4 cp.async.bulk 32B row copies into a
// 32KB smem tile (mbarrier completion), then the block flushes coalesced.

static constexpr unsigned P1 = 2654435761u;
static constexpr unsigned P2 = 805459861u;
static constexpr unsigned HASH_MASK = 524288u - 1u;  // 2^19
static constexpr int THREADS = 256;
static constexpr int PTS_PER_BLOCK = 1024;           // 32 KB tile

__device__ __forceinline__ unsigned hash3f(float a, float b, float c)
{
    unsigned u0 = (unsigned)__float2int_rz(a * 128.0f);
    unsigned u1 = (unsigned)__float2int_rz(b * 128.0f);
    unsigned u2 = (unsigned)__float2int_rz(c * 128.0f);
    return (u0 ^ (u1 * P1) ^ (u2 * P2)) & HASH_MASK;
}

__global__ void __launch_bounds__(THREADS)
hashgrid_tma_all_kernel(const float4* __restrict__ x4,
                        const char* __restrict__ emb,   // [H] rows of 32B
                        float4* __restrict__ out)       // [N][2] float4
{
    __shared__ __align__(128) float4 tile[PTS_PER_BLOCK * 2];  // 32 KB
    __shared__ __align__(8) unsigned long long mbar;

    const int tid = threadIdx.x;
    unsigned bar_a  = (unsigned)__cvta_generic_to_shared(&mbar);
    unsigned tile_a = (unsigned)__cvta_generic_to_shared(tile);

    if (tid == 0) {
        asm volatile("mbarrier.init.shared.b64 [%0], 1;" :: "r"(bar_a) : "memory");
        asm volatile("mbarrier.arrive.expect_tx.shared.b64 _, [%0], %1;"
                     :: "r"(bar_a), "r"(PTS_PER_BLOCK * 32) : "memory");
    }
    __syncthreads();

    // ---- phase 1: hash 4 consecutive points (12 floats = 3 float4), issue
    //      4 bulk 32B row gathers into this thread's tile slots ----
    {
        size_t xb = (size_t)blockIdx.x * (PTS_PER_BLOCK * 3 / 4) + 3 * tid;
        float4 a = __ldg(&x4[xb + 0]);
        float4 b = __ldg(&x4[xb + 1]);
        float4 c = __ldg(&x4[xb + 2]);

        unsigned h0 = hash3f(a.x, a.y, a.z);
        unsigned h1 = hash3f(a.w, b.x, b.y);
        unsigned h2 = hash3f(b.z, b.w, c.x);
        unsigned h3 = hash3f(c.y, c.z, c.w);

        unsigned dst = tile_a + (unsigned)tid * 128u;  // 4 pts * 32 B
#define BULK32(H, OFF)                                                        \
        asm volatile(                                                         \
            "cp.async.bulk.shared::cta.global.mbarrier::complete_tx::bytes "  \
            "[%0], [%1], 32, [%2];"                                           \
            :: "r"(dst + (OFF)),                                              \
               "l"(emb + (size_t)(H) * 32u), "r"(bar_a) : "memory")
        BULK32(h0, 0u);
        BULK32(h1, 32u);
        BULK32(h2, 64u);
        BULK32(h3, 96u);
#undef BULK32
    }

    // ---- phase 2: wait for all 32 KB, flush coalesced ----
    asm volatile(
        "{\n\t"
        ".reg .pred P;\n\t"
        "WAIT_%=:\n\t"
        "mbarrier.try_wait.parity.acquire.cta.shared::cta.b64 P, [%0], 0, 0x989680;\n\t"
        "@P bra.uni DONE_%=;\n\t"
        "bra.uni WAIT_%=;\n\t"
        "DONE_%=:\n\t"
        "}"
        :: "r"(bar_a) : "memory");

    float4* o4 = out + (size_t)blockIdx.x * (PTS_PER_BLOCK * 2);
#pragma unroll
    for (int k = 0; k < 8; k++)
        o4[tid + 256 * k] = tile[tid + 256 * k];
}

// ---------------- fallback (proven R3) for non-multiple sizes ----------------

__global__ void __launch_bounds__(THREADS)
hashgrid_gather_ilp4_kernel(const float* __restrict__ x,
                            const float4* __restrict__ emb,
                            float4* __restrict__ out,
                            int n)
{
    int tid  = threadIdx.x;
    int w    = tid >> 5;
    int lane = tid & 31;
    int qw   = lane >> 1;
    int half = lane & 1;
    int base = blockIdx.x * 512 + w * 64 + qw;

    float xv[4][3];
#pragma unroll
    for (int k = 0; k < 4; k++) {
        int p = base + 16 * k;
        if (p < n) {
            xv[k][0] = x[3 * p + 0];
            xv[k][1] = x[3 * p + 1];
            xv[k][2] = x[3 * p + 2];
        }
    }
    unsigned h[4];
#pragma unroll
    for (int k = 0; k < 4; k++)
        h[k] = hash3f(xv[k][0], xv[k][1], xv[k][2]);

    float4 v[4];
#pragma unroll
    for (int k = 0; k < 4; k++)
        if (base + 16 * k < n) v[k] = __ldg(&emb[2 * h[k] + half]);
#pragma unroll
    for (int k = 0; k < 4; k++) {
        int p = base + 16 * k;
        if (p < n) out[2 * p + half] = v[k];
    }
}

extern "C" void kernel_launch(void* const* d_in, const int* in_sizes, int n_in,
                              void* d_out, int out_size)
{
    const float* x   = (const float*)d_in[0];
    const char*  emb = (const char*)d_in[1];
    float4*      out = (float4*)d_out;

    int n = in_sizes[0] / 3;  // N_POINTS

    if (n % PTS_PER_BLOCK == 0) {
        int blocks = n / PTS_PER_BLOCK;  // 2048
        hashgrid_tma_all_kernel<<<blocks, THREADS>>>(
            (const float4*)x, emb, out);
    } else {
        int blocks = (n + 511) / 512;
        hashgrid_gather_ilp4_kernel<<<blocks, THREADS>>>(
            x, (const float4*)emb, out, n);
    }
}